// round 1
// baseline (speedup 1.0000x reference)
#include <cuda_runtime.h>
#include <cstdint>

// Problem constants
#define NN   65536   // nodes
#define BB   128     // batch
#define TT   16      // timesteps
#define IBK  256     // input bits per step (w_in = arange(IBK))
#define OO   10      // readout outputs

// ---------------- static device scratch (no allocations allowed) ----------------
// state double buffer: 128 bits per node, batch-packed. bit (b&31) of word (b>>5).
__device__ uint4    g_state[2][NN];          // 2 x 1MB
__device__ unsigned g_lut[NN * 8];           // 2MB: 256-bit LUT row per node, bit i of word w = lut[n][w*32+i]
__device__ uint4    g_xp[TT * IBK];          // per-step batch-packed input bits, indexed by node (<IBK)
__device__ float    g_partial[256 * 128 * OO]; // readout partials [chunk 0..255][b][o]

// ---------------- preprocessing: pack lut bits (64MB -> 2MB) ----------------
__global__ void pack_lut_kernel(const int* __restrict__ lut) {
    int gw   = (blockIdx.x * blockDim.x + threadIdx.x) >> 5;  // node id, exact grid
    int lane = threadIdx.x & 31;
    const int* row = lut + (size_t)gw * 256;
    unsigned myword = 0;
    #pragma unroll
    for (int w = 0; w < 8; w++) {
        int v = row[w * 32 + lane];
        unsigned bal = __ballot_sync(0xFFFFFFFFu, v & 1);
        if (lane == w) myword = bal;
    }
    if (lane < 8) g_lut[gw * 8 + lane] = myword;
}

// ---------------- preprocessing: pack x into batch-bit words ----------------
// g_xp[t*IBK + node] word w bit l = x[b=32w+l][t][i] where node = w_in[i]
__global__ void pack_x_kernel(const int* __restrict__ x, const int* __restrict__ w_in) {
    int gw   = (blockIdx.x * blockDim.x + threadIdx.x) >> 5;  // 0..TT*IBK-1, exact grid
    int lane = threadIdx.x & 31;
    int t = gw >> 8;
    int i = gw & 255;
    unsigned b0, b1, b2, b3;
    {
        int b = 0 * 32 + lane; int v = x[(b * TT + t) * IBK + i];
        b0 = __ballot_sync(0xFFFFFFFFu, v & 1);
    }
    {
        int b = 1 * 32 + lane; int v = x[(b * TT + t) * IBK + i];
        b1 = __ballot_sync(0xFFFFFFFFu, v & 1);
    }
    {
        int b = 2 * 32 + lane; int v = x[(b * TT + t) * IBK + i];
        b2 = __ballot_sync(0xFFFFFFFFu, v & 1);
    }
    {
        int b = 3 * 32 + lane; int v = x[(b * TT + t) * IBK + i];
        b3 = __ballot_sync(0xFFFFFFFFu, v & 1);
    }
    if (lane == 0) {
        int node = w_in[i];                     // arange -> node == i (< IBK)
        if ((unsigned)node < IBK) {
            uint4 v; v.x = b0; v.y = b1; v.z = b2; v.w = b3;
            g_xp[t * IBK + node] = v;
        }
    }
}

// ---------------- init: broadcast init_state across batch, fuse x[t=0] XOR ----------------
__global__ void init_state_kernel(const int* __restrict__ init_state) {
    int n = blockIdx.x * blockDim.x + threadIdx.x;
    unsigned v = (unsigned)(-(init_state[n] & 1));  // 0 or 0xFFFFFFFF
    uint4 s; s.x = v; s.y = v; s.z = v; s.w = v;
    if (n < IBK) {
        uint4 xv = g_xp[n];     // t = 0
        s.x ^= xv.x; s.y ^= xv.y; s.z ^= xv.z; s.w ^= xv.w;
    }
    g_state[0][n] = s;
}

// ---------------- one reservoir step ----------------
// thread <-> node. gather 8 neighbor 128-bit words, bit-transpose to 128 idx bytes,
// LUT lookup from shared-staged packed row, write new 128-bit word (+fused x XOR for t+1).
__global__ void __launch_bounds__(256) step_kernel(const int* __restrict__ adj,
                                                   const int* __restrict__ adj_mask,
                                                   int t) {
    __shared__ unsigned slut[256 * 9];   // padded stride 9 to spread banks
    const int n = blockIdx.x * 256 + threadIdx.x;
    const uint4* __restrict__ sin  = g_state[t & 1];
    uint4* __restrict__       sout = g_state[(t + 1) & 1];

    // stage this node's packed LUT row (32B) into shared
    unsigned* myl = &slut[threadIdx.x * 9];
    {
        const uint4* lr = (const uint4*)&g_lut[n * 8];
        uint4 lA = __ldg(lr);
        uint4 lB = __ldg(lr + 1);
        myl[0] = lA.x; myl[1] = lA.y; myl[2] = lA.z; myl[3] = lA.w;
        myl[4] = lB.x; myl[5] = lB.y; myl[6] = lB.z; myl[7] = lB.w;
    }

    // adjacency + mask rows (32B each)
    const int4* adj4 = (const int4*)adj;
    const int4* msk4 = (const int4*)adj_mask;
    int4 a0 = __ldg(&adj4[n * 2]);
    int4 a1 = __ldg(&adj4[n * 2 + 1]);
    int4 m0 = __ldg(&msk4[n * 2]);
    int4 m1 = __ldg(&msk4[n * 2 + 1]);

    int jj[8] = { a0.x, a0.y, a0.z, a0.w, a1.x, a1.y, a1.z, a1.w };
    int mk[8] = { m0.x, m0.y, m0.z, m0.w, m1.x, m1.y, m1.z, m1.w };

    // gather neighbor batch-words (mask==0 -> zero contribution)
    unsigned nbw[8][4];
    #pragma unroll
    for (int k = 0; k < 8; k++) {
        uint4 v = __ldg(&sin[jj[k]]);
        unsigned mm = (mk[k] != 0) ? 0xFFFFFFFFu : 0u;
        nbw[k][0] = v.x & mm; nbw[k][1] = v.y & mm;
        nbw[k][2] = v.z & mm; nbw[k][3] = v.w & mm;
    }

    unsigned outw[4];
    #pragma unroll
    for (int l = 0; l < 4; l++) {     // 32 batches per lane word
        unsigned r0 = nbw[0][l], r1 = nbw[1][l], r2 = nbw[2][l], r3 = nbw[3][l];
        unsigned r4 = nbw[4][l], r5 = nbw[5][l], r6 = nbw[6][l], r7 = nbw[7][l];
        unsigned acc = 0;
        #pragma unroll
        for (int g = 0; g < 4; g++) { // byte group = 8 batches
            const unsigned s01 = (unsigned)(g | ((g + 4) << 4));
            // pack byte g of n7..n0 into u64, byte r = n_{7-r}.byte[g]
            unsigned t76 = __byte_perm(r7, r6, s01);
            unsigned t54 = __byte_perm(r5, r4, s01);
            unsigned t32 = __byte_perm(r3, r2, s01);
            unsigned t10 = __byte_perm(r1, r0, s01);
            unsigned lo  = __byte_perm(t76, t54, 0x5410);
            unsigned hi  = __byte_perm(t32, t10, 0x5410);
            unsigned long long xx = (unsigned long long)lo | ((unsigned long long)hi << 32);
            // 8x8 bit transpose (Hacker's Delight masked swaps)
            unsigned long long tt;
            tt = (xx ^ (xx >> 7))  & 0x00AA00AA00AA00AAULL; xx ^= tt ^ (tt << 7);
            tt = (xx ^ (xx >> 14)) & 0x0000CCCC0000CCCCULL; xx ^= tt ^ (tt << 14);
            tt = (xx ^ (xx >> 28)) & 0x00000000F0F0F0F0ULL; xx ^= tt ^ (tt << 28);
            unsigned xl = (unsigned)xx;
            unsigned xh = (unsigned)(xx >> 32);
            // byte b of xx = 8-bit LUT index for batch 32l + 8g + b
            #pragma unroll
            for (int b = 0; b < 8; b++) {
                unsigned src = (b < 4) ? xl : xh;
                unsigned idx = __byte_perm(src, 0u, 0x4440u + (unsigned)(b & 3));
                unsigned w   = myl[idx >> 5];
                unsigned bit = (w >> (idx & 31)) & 1u;
                acc |= bit << (g * 8 + b);
            }
        }
        outw[l] = acc;
    }

    uint4 o; o.x = outw[0]; o.y = outw[1]; o.z = outw[2]; o.w = outw[3];
    // fuse next step's input XOR (state entering step t+1)
    if (t < TT - 1 && n < IBK) {
        uint4 xv = g_xp[(t + 1) * IBK + n];
        o.x ^= xv.x; o.y ^= xv.y; o.z ^= xv.z; o.w ^= xv.w;
    }
    sout[n] = o;
}

// ---------------- readout phase 1: deterministic partials ----------------
// grid 128 CTAs x 256 threads. CTA c owns nodes [c*512, c*512+512).
// thread: sub = tid>>7 (node half), b = tid&127 (batch). acc over 256 nodes.
__global__ void readout_kernel(const float* __restrict__ wro) {
    int c   = blockIdx.x;
    int b   = threadIdx.x & 127;
    int sub = threadIdx.x >> 7;
    int wsel = b >> 5;
    int bit  = b & 31;
    float acc[OO];
    #pragma unroll
    for (int o = 0; o < OO; o++) acc[o] = 0.0f;

    const unsigned* st = (const unsigned*)g_state[0];  // final state after 16 steps
    int n0 = c * 512 + sub * 256;
    for (int n = n0; n < n0 + 256; n++) {
        unsigned wrd = __ldg(&st[n * 4 + wsel]);
        float f = (float)((wrd >> bit) & 1u);
        #pragma unroll
        for (int o = 0; o < OO; o++)
            acc[o] += f * __ldg(&wro[o * NN + n]);
    }
    float* p = &g_partial[(size_t)((c * 2 + sub) * 128 + b) * OO];
    #pragma unroll
    for (int o = 0; o < OO; o++) p[o] = acc[o];
}

// ---------------- readout phase 2: deterministic reduce + bias + sigmoid ----------------
__global__ void finalize_kernel(const float* __restrict__ b_readout, float* __restrict__ out) {
    int i = blockIdx.x * blockDim.x + threadIdx.x;  // 0..1279
    if (i >= BB * OO) return;
    int b = i / OO;
    int o = i % OO;
    float s = 0.0f;
    for (int c = 0; c < 256; c++)
        s += g_partial[(size_t)(c * 128 + b) * OO + o];
    s += b_readout[o];
    out[i] = 1.0f / (1.0f + expf(-s));
}

// ---------------- launch ----------------
extern "C" void kernel_launch(void* const* d_in, const int* in_sizes, int n_in,
                              void* d_out, int out_size) {
    const int*   x          = (const int*)d_in[0];
    const int*   adj_list   = (const int*)d_in[1];
    const int*   adj_mask   = (const int*)d_in[2];
    const int*   lut        = (const int*)d_in[3];
    const int*   init_state = (const int*)d_in[4];
    const int*   w_in       = (const int*)d_in[5];
    const float* w_readout  = (const float*)d_in[6];
    const float* b_readout  = (const float*)d_in[7];
    float*       out        = (float*)d_out;

    pack_lut_kernel<<<(NN * 32) / 256, 256>>>(lut);        // 8192 blocks
    pack_x_kernel<<<(TT * IBK * 32) / 256, 256>>>(x, w_in); // 512 blocks
    init_state_kernel<<<NN / 256, 256>>>(init_state);       // 256 blocks
    for (int t = 0; t < TT; t++)
        step_kernel<<<NN / 256, 256>>>(adj_list, adj_mask, t);
    readout_kernel<<<128, 256>>>(w_readout);
    finalize_kernel<<<(BB * OO + 255) / 256, 256>>>(b_readout, out);
}